// round 5
// baseline (speedup 1.0000x reference)
#include <cuda_runtime.h>
#include <cuda_bf16.h>

// ---------------- problem constants ----------------
#define LDIM 1024
#define CZ   128
#define CS   1024
#define KSPL 3840            // 3*1280 split-K for final projection
#define ASTRIDE 136          // padded bf16 row stride (conflict-free LDS frags)
#define NSUB  19
#define NMBLK 8
#define GRID_MAIN (NSUB * NMBLK)   // 152 CTAs = 152 SMs on GB300

// ---------------- device scratch ----------------
__device__ __align__(16) float g_sc[LDIM * CZ];          // sum_m mask*h (per l)
__device__ __align__(16) float g_sr[LDIM * CZ];          // sum_l mask*h (per m)
__device__ float g_nc[LDIM];
__device__ float g_nr[LDIM];
__device__ __align__(16) __nv_bfloat16 g_w1b[CZ * ASTRIDE];
__device__ __align__(16) __nv_bfloat16 g_wcb[(size_t)CS * KSPL];   // [hiW | loW | hiW]
__device__ __align__(16) __nv_bfloat16 g_catb[(size_t)LDIM * KSPL];// [hiA | hiA | loA]

// ---------------- mma helper ----------------
__device__ __forceinline__ void mma16816(float* d, const unsigned* a, const unsigned* b) {
    asm volatile(
        "mma.sync.aligned.m16n8k16.row.col.f32.bf16.bf16.f32 "
        "{%0,%1,%2,%3}, {%4,%5,%6,%7}, {%8,%9}, {%0,%1,%2,%3};\n"
        : "+f"(d[0]), "+f"(d[1]), "+f"(d[2]), "+f"(d[3])
        : "r"(a[0]), "r"(a[1]), "r"(a[2]), "r"(a[3]), "r"(b[0]), "r"(b[1]));
}

// 128x128x128 bf16 GEMM: A row-major [128][ASTRIDE], B = W [n][k] row-major [128][ASTRIDE]
__device__ __forceinline__ void gemm128(const __nv_bfloat16* __restrict__ A,
                                        const __nv_bfloat16* __restrict__ B,
                                        float d[2][8][4], int wm, int wn, int lane) {
#pragma unroll
    for (int kk = 0; kk < 8; ++kk) {
        const int k0 = kk * 16 + (lane & 3) * 2;
        unsigned a[2][4], b[8][2];
#pragma unroll
        for (int mt = 0; mt < 2; ++mt) {
            const int r = wm * 32 + mt * 16 + (lane >> 2);
            a[mt][0] = *(const unsigned*)(A + r * ASTRIDE + k0);
            a[mt][1] = *(const unsigned*)(A + (r + 8) * ASTRIDE + k0);
            a[mt][2] = *(const unsigned*)(A + r * ASTRIDE + k0 + 8);
            a[mt][3] = *(const unsigned*)(A + (r + 8) * ASTRIDE + k0 + 8);
        }
#pragma unroll
        for (int nt = 0; nt < 8; ++nt) {
            const int n = wn * 64 + nt * 8 + (lane >> 2);
            b[nt][0] = *(const unsigned*)(B + n * ASTRIDE + k0);
            b[nt][1] = *(const unsigned*)(B + n * ASTRIDE + k0 + 8);
        }
#pragma unroll
        for (int mt = 0; mt < 2; ++mt)
#pragma unroll
            for (int nt = 0; nt < 8; ++nt) mma16816(d[mt][nt], a[mt], b[nt]);
    }
}

__device__ __forceinline__ void cp_async16(void* sptr, const void* gptr) {
    unsigned s = (unsigned)__cvta_generic_to_shared(sptr);
    asm volatile("cp.async.cg.shared.global [%0], [%1], 16;\n" :: "r"(s), "l"(gptr));
}

// ---------------- prep kernels ----------------
__global__ void prep_w1(const float* __restrict__ w1) {
    int i = blockIdx.x * 256 + threadIdx.x;
    if (i >= CZ * ASTRIDE) return;
    int d = i / ASTRIDE, k = i % ASTRIDE;
    g_w1b[i] = __float2bfloat16((k < CZ) ? w1[d * CZ + k] : 0.f);
}

__global__ void prep_wc(const float* __restrict__ wc) {
    int i = blockIdx.x * 256 + threadIdx.x;
    if (i >= CS * 1280) return;
    int d = i / 1280, k = i % 1280;
    float v = wc[i];
    __nv_bfloat16 hi = __float2bfloat16(v);
    __nv_bfloat16 lo = __float2bfloat16(v - __bfloat162float(hi));
    size_t base = (size_t)d * KSPL;
    g_wcb[base + k] = hi;
    g_wcb[base + 1280 + k] = lo;
    g_wcb[base + 2560 + k] = hi;
}

__global__ void zero_acc() {
    int i = blockIdx.x * 256 + threadIdx.x;
    if (i < LDIM * CZ) { g_sc[i] = 0.f; g_sr[i] = 0.f; }
}

// coalesced row + column mask sums
__global__ void norm2(const float* __restrict__ mask) {
    const int b = blockIdx.x, t = threadIdx.x;   // block 128
    if (b < LDIM) {
        const float* p = mask + (size_t)b * LDIM;
        float s = 0.f;
#pragma unroll
        for (int i = 0; i < 8; ++i) s += p[t + i * 128];
#pragma unroll
        for (int o = 16; o; o >>= 1) s += __shfl_xor_sync(0xffffffffu, s, o);
        __shared__ float ws[4];
        if ((t & 31) == 0) ws[t >> 5] = s;
        __syncthreads();
        if (t == 0) g_nc[b] = ws[0] + ws[1] + ws[2] + ws[3];
    } else {
        const int m = (b - LDIM) * 128 + t;
        float s = 0.f;
#pragma unroll 8
        for (int l_ = 0; l_ < LDIM; ++l_) s += mask[(size_t)l_ * LDIM + m];
        g_nr[m] = s;
    }
}

// ---------------- main fused kernel: prefetch -> LN -> GEMM1 -> relu/mask h-sums ----------------
#define SMEM_MAIN (131072 + 34816 + 34816 + 512 + 1024 + 1024)

__global__ __launch_bounds__(256, 1)
void main_kernel(const float* __restrict__ s_z, const float* __restrict__ mask,
                 const float* __restrict__ ln_g, const float* __restrict__ ln_b,
                 const float* __restrict__ b1p) {
    extern __shared__ __align__(16) char smem_raw[];
    float* sZ = (float*)smem_raw;                          // [2][16384] fp32
    __nv_bfloat16* sA  = (__nv_bfloat16*)(sZ + 2 * 16384); // LN output
    __nv_bfloat16* sW1 = sA + CZ * ASTRIDE;
    float* sB1    = (float*)(sW1 + CZ * ASTRIDE);          // [128]
    float* sMaskB = sB1 + CZ;                              // [2][128]
    float* sCSB   = sMaskB + 2 * CZ;                       // [2][128]

    const int tid = threadIdx.x, lane = tid & 31, wid = tid >> 5;
    const int wm = wid & 3, wn = wid >> 2;
    const int cta = blockIdx.x;
    const int mblk = cta / NSUB, sub = cta % NSUB;
    const int l0 = (sub * LDIM) / NSUB, l1 = ((sub + 1) * LDIM) / NSUB;
    const int m0 = mblk * 128;

    for (int i = tid; i < CZ * ASTRIDE / 4; i += 256)
        ((uint2*)sW1)[i] = ((const uint2*)g_w1b)[i];
    if (tid < CZ) sB1[tid] = b1p[tid];
    if (tid < 2 * CZ) sCSB[tid] = 0.f;
    const float4 gg = ((const float4*)ln_g)[lane];
    const float4 bb = ((const float4*)ln_b)[lane];

    float sr_acc[2][8][4];
#pragma unroll
    for (int mt = 0; mt < 2; ++mt)
#pragma unroll
        for (int nt = 0; nt < 8; ++nt)
#pragma unroll
            for (int j = 0; j < 4; ++j) sr_acc[mt][nt][j] = 0.f;

    // prologue prefetch of l0
    {
        const float* src = s_z + (((size_t)l0 * LDIM + m0) << 7);
        for (int i = tid; i < 4096; i += 256) cp_async16(sZ + (size_t)i * 4, src + (size_t)i * 4);
        if (tid < 32) cp_async16(sMaskB + tid * 4, mask + (size_t)l0 * LDIM + m0 + tid * 4);
        asm volatile("cp.async.commit_group;\n");
    }

    for (int l = l0; l < l1; ++l) {
        const int buf = (l - l0) & 1;
        if (l + 1 < l1) {
            const int nb = buf ^ 1;
            const float* src = s_z + (((size_t)(l + 1) * LDIM + m0) << 7);
            float* dst = sZ + nb * 16384;
            for (int i = tid; i < 4096; i += 256) cp_async16(dst + (size_t)i * 4, src + (size_t)i * 4);
            if (tid < 32) cp_async16(sMaskB + nb * CZ + tid * 4,
                                     mask + (size_t)(l + 1) * LDIM + m0 + tid * 4);
            asm volatile("cp.async.commit_group;\n");
            asm volatile("cp.async.wait_group 1;\n");
        } else {
            asm volatile("cp.async.wait_group 0;\n");
        }
        __syncthreads();

        // ---- LayerNorm from smem: 8 warps x 16 rows ----
        const float* zb = sZ + buf * 16384;
#pragma unroll 4
        for (int j = 0; j < 16; ++j) {
            const int row = wid * 16 + j;
            float4 x = ((const float4*)(zb + row * 128))[lane];
            float s = x.x + x.y + x.z + x.w;
            float q = fmaf(x.x, x.x, fmaf(x.y, x.y, fmaf(x.z, x.z, x.w * x.w)));
#pragma unroll
            for (int o = 16; o; o >>= 1) {
                s += __shfl_xor_sync(0xffffffffu, s, o);
                q += __shfl_xor_sync(0xffffffffu, q, o);
            }
            const float mu = s * (1.f / 128.f);
            const float var = q * (1.f / 128.f) - mu * mu;
            const float rstd = rsqrtf(var + 1e-5f);
            const float y0 = (x.x - mu) * rstd * gg.x + bb.x;
            const float y1 = (x.y - mu) * rstd * gg.y + bb.y;
            const float y2 = (x.z - mu) * rstd * gg.z + bb.z;
            const float y3 = (x.w - mu) * rstd * gg.w + bb.w;
            __nv_bfloat162 p0 = __floats2bfloat162_rn(y0, y1);
            __nv_bfloat162 p1 = __floats2bfloat162_rn(y2, y3);
            uint2 pk = make_uint2(*(unsigned*)&p0, *(unsigned*)&p1);
            *reinterpret_cast<uint2*>(sA + row * ASTRIDE + lane * 4) = pk;
        }
        __syncthreads();

        // ---- GEMM1 -> h = relu(.+b1); accumulate mask-weighted row/col sums of h ----
        float d1[2][8][4] = {};
        gemm128(sA, sW1, d1, wm, wn, lane);

        const float* mk = sMaskB + buf * CZ;
        float* cs_s = sCSB + buf * CZ;
        float cs[8][2];
#pragma unroll
        for (int nt = 0; nt < 8; ++nt) { cs[nt][0] = 0.f; cs[nt][1] = 0.f; }
#pragma unroll
        for (int mt = 0; mt < 2; ++mt)
#pragma unroll
            for (int nt = 0; nt < 8; ++nt) {
                const int r = wm * 32 + mt * 16 + (lane >> 2);
                const int c = wn * 64 + nt * 8 + (lane & 3) * 2;
                const float mk0 = mk[r], mk8 = mk[r + 8];
                const float bv0 = sB1[c], bv1 = sB1[c + 1];
                const float v0 = fmaxf(d1[mt][nt][0] + bv0, 0.f) * mk0;
                const float v1 = fmaxf(d1[mt][nt][1] + bv1, 0.f) * mk0;
                const float v2 = fmaxf(d1[mt][nt][2] + bv0, 0.f) * mk8;
                const float v3 = fmaxf(d1[mt][nt][3] + bv1, 0.f) * mk8;
                sr_acc[mt][nt][0] += v0; sr_acc[mt][nt][1] += v1;
                sr_acc[mt][nt][2] += v2; sr_acc[mt][nt][3] += v3;
                cs[nt][0] += v0 + v2;
                cs[nt][1] += v1 + v3;
            }
#pragma unroll
        for (int nt = 0; nt < 8; ++nt) {
#pragma unroll
            for (int o = 4; o <= 16; o <<= 1) {
                cs[nt][0] += __shfl_xor_sync(0xffffffffu, cs[nt][0], o);
                cs[nt][1] += __shfl_xor_sync(0xffffffffu, cs[nt][1], o);
            }
        }
        if (lane < 4) {
#pragma unroll
            for (int nt = 0; nt < 8; ++nt) {
                const int c = wn * 64 + nt * 8 + lane * 2;
                atomicAdd(&cs_s[c], cs[nt][0]);
                atomicAdd(&cs_s[c + 1], cs[nt][1]);
            }
        }
        __syncthreads();
        if (wid == 0) {
#pragma unroll
            for (int j = 0; j < 4; ++j) {
                const int c = j * 32 + lane;
                atomicAdd(&g_sc[l * CZ + c], cs_s[c]);
                cs_s[c] = 0.f;
            }
        }
    }

    // ---- flush per-m masked h sums ----
#pragma unroll
    for (int mt = 0; mt < 2; ++mt)
#pragma unroll
        for (int nt = 0; nt < 8; ++nt) {
            const int r = wm * 32 + mt * 16 + (lane >> 2);
            const int c = wn * 64 + nt * 8 + (lane & 3) * 2;
            atomicAdd(&g_sr[(size_t)(m0 + r) * CZ + c],     sr_acc[mt][nt][0]);
            atomicAdd(&g_sr[(size_t)(m0 + r) * CZ + c + 1], sr_acc[mt][nt][1]);
            atomicAdd(&g_sr[(size_t)(m0 + r + 8) * CZ + c],     sr_acc[mt][nt][2]);
            atomicAdd(&g_sr[(size_t)(m0 + r + 8) * CZ + c + 1], sr_acc[mt][nt][3]);
        }
}

// ---------------- finalize: s_c = (W2 @ hsum_c + b2*nc)/max(nc,1); same for rows; build cat ----
#define SMEM_CATF (128 * 132 * 4 + 512 + 1024 + 1024)

__global__ __launch_bounds__(256)
void cat_finalize(const float* __restrict__ w2, const float* __restrict__ b2,
                  const float* __restrict__ s_s_in) {
    extern __shared__ __align__(16) char cf_raw[];
    float* sw2  = (float*)cf_raw;          // [128][132]
    float* sb2  = sw2 + 128 * 132;
    float* sh   = sb2 + 128;               // [256] : hsum_c | hsum_r
    float* sval = sh + 256;                // [256]
    const int tid = threadIdx.x;

    for (int i = tid; i < 128 * 32; i += 256) {
        int r = i >> 5, kq = i & 31;
        ((float4*)(sw2 + r * 132))[kq] = ((const float4*)(w2 + r * 128))[kq];
    }
    if (tid < 128) sb2[tid] = b2[tid];
    __syncthreads();

    for (int li = 0; li < 16; ++li) {
        const int l = blockIdx.x * 16 + li;
        if (tid < 128) sh[tid] = g_sc[l * CZ + tid];
        else           sh[tid] = g_sr[l * CZ + (tid - 128)];
        __syncthreads();
        const int c = tid & 127;
        const float nraw = (tid < 128) ? g_nc[l] : g_nr[l];
        const float* hv = sh + (tid & 128);
        float acc = sb2[c] * nraw;
#pragma unroll 8
        for (int k = 0; k < 32; ++k) {
            float4 w = ((const float4*)(sw2 + c * 132))[k];
            float4 h = ((const float4*)hv)[k];
            acc += w.x * h.x + w.y * h.y + w.z * h.z + w.w * h.w;
        }
        sval[tid] = acc / fmaxf(nraw, 1.f);
        __syncthreads();
        const size_t base = (size_t)l * KSPL;
        for (int k = tid; k < 1280; k += 256) {
            float v = (k < 256) ? sval[k] : s_s_in[(size_t)l * CS + (k - 256)];
            __nv_bfloat16 hi = __float2bfloat16(v);
            __nv_bfloat16 lo = __float2bfloat16(v - __bfloat162float(hi));
            g_catb[base + k] = hi;
            g_catb[base + 1280 + k] = hi;
            g_catb[base + 2560 + k] = lo;
        }
        __syncthreads();
    }
}

// ---------------- final projection GEMM: [1024 x 3840] @ [1024 x 3840]^T ----------------
__global__ __launch_bounds__(256, 2)
void final_gemm(const float* __restrict__ bc, float* __restrict__ out) {
    __shared__ __align__(16) __nv_bfloat16 sA[2][64 * 72];
    __shared__ __align__(16) __nv_bfloat16 sB[2][64 * 72];
    const int tid = threadIdx.x, lane = tid & 31, wid = tid >> 5;
    const int wm = wid & 3, wn = wid >> 2;
    const int lbase = blockIdx.y * 64, dbase = blockIdx.x * 64;
    const int NCH = KSPL / 64;   // 60

    float acc[4][4];
#pragma unroll
    for (int nt = 0; nt < 4; ++nt)
#pragma unroll
        for (int j = 0; j < 4; ++j) acc[nt][j] = 0.f;

    {
        for (int i = tid; i < 512; i += 256) {
            int row = i >> 3, seg = i & 7;
            cp_async16(&sA[0][row * 72 + seg * 8], &g_catb[(size_t)(lbase + row) * KSPL + seg * 8]);
            cp_async16(&sB[0][row * 72 + seg * 8], &g_wcb[(size_t)(dbase + row) * KSPL + seg * 8]);
        }
        asm volatile("cp.async.commit_group;\n");
    }

    for (int ch = 0; ch < NCH; ++ch) {
        const int buf = ch & 1;
        if (ch + 1 < NCH) {
            const size_t kb = (size_t)(ch + 1) * 64;
            const int nb = buf ^ 1;
            for (int i = tid; i < 512; i += 256) {
                int row = i >> 3, seg = i & 7;
                cp_async16(&sA[nb][row * 72 + seg * 8], &g_catb[(size_t)(lbase + row) * KSPL + kb + seg * 8]);
                cp_async16(&sB[nb][row * 72 + seg * 8], &g_wcb[(size_t)(dbase + row) * KSPL + kb + seg * 8]);
            }
            asm volatile("cp.async.commit_group;\n");
            asm volatile("cp.async.wait_group 1;\n");
        } else {
            asm volatile("cp.async.wait_group 0;\n");
        }
        __syncthreads();
#pragma unroll
        for (int kk = 0; kk < 4; ++kk) {
            const int k0 = kk * 16 + (lane & 3) * 2;
            const int r = wm * 16 + (lane >> 2);
            unsigned a[4], b[4][2];
            a[0] = *(const unsigned*)&sA[buf][r * 72 + k0];
            a[1] = *(const unsigned*)&sA[buf][(r + 8) * 72 + k0];
            a[2] = *(const unsigned*)&sA[buf][r * 72 + k0 + 8];
            a[3] = *(const unsigned*)&sA[buf][(r + 8) * 72 + k0 + 8];
#pragma unroll
            for (int nt = 0; nt < 4; ++nt) {
                const int n = wn * 32 + nt * 8 + (lane >> 2);
                b[nt][0] = *(const unsigned*)&sB[buf][n * 72 + k0];
                b[nt][1] = *(const unsigned*)&sB[buf][n * 72 + k0 + 8];
            }
#pragma unroll
            for (int nt = 0; nt < 4; ++nt) mma16816(acc[nt], a, b[nt]);
        }
        __syncthreads();
    }

#pragma unroll
    for (int nt = 0; nt < 4; ++nt) {
        const int r = wm * 16 + (lane >> 2);
        const int c = wn * 32 + nt * 8 + (lane & 3) * 2;
        const int gr = lbase + r, gc = dbase + c;
        const float b0 = __ldg(&bc[gc]), b1v = __ldg(&bc[gc + 1]);
        out[(size_t)gr * CS + gc]           = acc[nt][0] + b0;
        out[(size_t)gr * CS + gc + 1]       = acc[nt][1] + b1v;
        out[(size_t)(gr + 8) * CS + gc]     = acc[nt][2] + b0;
        out[(size_t)(gr + 8) * CS + gc + 1] = acc[nt][3] + b1v;
    }
}

// ---------------- launcher ----------------
extern "C" void kernel_launch(void* const* d_in, const int* in_sizes, int n_in,
                              void* d_out, int out_size) {
    const float* s_z    = (const float*)d_in[0];
    const float* s_s_in = (const float*)d_in[1];
    const float* mask   = (const float*)d_in[2];
    const float* ln_g   = (const float*)d_in[3];
    const float* ln_b   = (const float*)d_in[4];
    const float* w1     = (const float*)d_in[5];
    const float* b1     = (const float*)d_in[6];
    const float* w2     = (const float*)d_in[7];
    const float* b2     = (const float*)d_in[8];
    const float* wc     = (const float*)d_in[9];
    const float* bc     = (const float*)d_in[10];
    float* out = (float*)d_out;
    (void)in_sizes; (void)n_in; (void)out_size;

    cudaFuncSetAttribute(main_kernel, cudaFuncAttributeMaxDynamicSharedMemorySize, SMEM_MAIN);
    cudaFuncSetAttribute(cat_finalize, cudaFuncAttributeMaxDynamicSharedMemorySize, SMEM_CATF);

    prep_w1<<<(CZ * ASTRIDE + 255) / 256, 256>>>(w1);
    prep_wc<<<(CS * 1280 + 255) / 256, 256>>>(wc);
    zero_acc<<<(LDIM * CZ + 255) / 256, 256>>>();
    norm2<<<LDIM + 8, 128>>>(mask);
    main_kernel<<<GRID_MAIN, 256, SMEM_MAIN>>>(s_z, mask, ln_g, ln_b, b1);
    cat_finalize<<<64, 256, SMEM_CATF>>>(w2, b2, s_s_in);
    final_gemm<<<dim3(16, 16), 256>>>(bc, out);
}

// round 6
// speedup vs baseline: 1.4918x; 1.4918x over previous
#include <cuda_runtime.h>
#include <cuda_bf16.h>

// ---------------- problem constants ----------------
#define LDIM 1024
#define CZ   128
#define CS   1024
#define KCAT 1280
#define ASTRIDE 136          // padded bf16 row stride
#define ZSTRIDE 132          // padded fp32 row stride for sZ
#define NSUB  19
#define NMBLK 8
#define GRID_MAIN (NSUB * NMBLK)   // 152

// ---------------- device scratch ----------------
__device__ __align__(16) float g_sc[LDIM * CZ];
__device__ __align__(16) float g_sr[LDIM * CZ];
__device__ float g_nc[LDIM];
__device__ float g_nr[LDIM];
__device__ __align__(16) __nv_bfloat16 g_w1b[CZ * ASTRIDE];
__device__ __align__(16) float g_wct[(size_t)CS * KCAT];   // tf32-rounded wc
__device__ __align__(16) float g_cat[(size_t)LDIM * KCAT]; // tf32-rounded [s_c|s_r|s_s_in]

// ---------------- helpers ----------------
__device__ __forceinline__ float to_tf32(float v) {
    float r; asm("cvt.rna.tf32.f32 %0, %1;" : "=f"(r) : "f"(v)); return r;
}
__device__ __forceinline__ void mma16816(float* d, const unsigned* a, const unsigned* b) {
    asm volatile(
        "mma.sync.aligned.m16n8k16.row.col.f32.bf16.bf16.f32 "
        "{%0,%1,%2,%3}, {%4,%5,%6,%7}, {%8,%9}, {%0,%1,%2,%3};\n"
        : "+f"(d[0]), "+f"(d[1]), "+f"(d[2]), "+f"(d[3])
        : "r"(a[0]), "r"(a[1]), "r"(a[2]), "r"(a[3]), "r"(b[0]), "r"(b[1]));
}
__device__ __forceinline__ void mma1688_tf32(float* d, const unsigned* a, const unsigned* b) {
    asm volatile(
        "mma.sync.aligned.m16n8k8.row.col.f32.tf32.tf32.f32 "
        "{%0,%1,%2,%3}, {%4,%5,%6,%7}, {%8,%9}, {%0,%1,%2,%3};\n"
        : "+f"(d[0]), "+f"(d[1]), "+f"(d[2]), "+f"(d[3])
        : "r"(a[0]), "r"(a[1]), "r"(a[2]), "r"(a[3]), "r"(b[0]), "r"(b[1]));
}
__device__ __forceinline__ void ldsm_x4(unsigned addr, unsigned& r0, unsigned& r1,
                                        unsigned& r2, unsigned& r3) {
    asm volatile("ldmatrix.sync.aligned.m8n8.x4.shared.b16 {%0,%1,%2,%3}, [%4];"
                 : "=r"(r0), "=r"(r1), "=r"(r2), "=r"(r3) : "r"(addr));
}
__device__ __forceinline__ void cp_async16(void* sptr, const void* gptr) {
    unsigned s = (unsigned)__cvta_generic_to_shared(sptr);
    asm volatile("cp.async.cg.shared.global [%0], [%1], 16;\n" :: "r"(s), "l"(gptr));
}

// ---------------- prep kernels ----------------
__global__ void prep_w1(const float* __restrict__ w1) {
    int i = blockIdx.x * 256 + threadIdx.x;
    if (i >= CZ * ASTRIDE) return;
    int d = i / ASTRIDE, k = i % ASTRIDE;
    g_w1b[i] = __float2bfloat16((k < CZ) ? w1[d * CZ + k] : 0.f);
}
__global__ void prep_wct(const float* __restrict__ wc) {
    int i = blockIdx.x * 256 + threadIdx.x;
    if (i < CS * KCAT) g_wct[i] = to_tf32(wc[i]);
}
__global__ void prep_catss(const float* __restrict__ s_s_in) {
    int i = blockIdx.x * 256 + threadIdx.x;          // over LDIM*CS
    if (i >= LDIM * CS) return;
    int l = i >> 10, k = i & 1023;
    g_cat[(size_t)l * KCAT + 256 + k] = to_tf32(s_s_in[i]);
}
__global__ void zero_acc() {
    int i = blockIdx.x * 256 + threadIdx.x;
    if (i < LDIM * CZ) { g_sc[i] = 0.f; g_sr[i] = 0.f; }
    if (i < LDIM) g_nr[i] = 0.f;
}
// coalesced mask row sums -> g_nc
__global__ void norm_c(const float* __restrict__ mask) {
    const int l = blockIdx.x, t = threadIdx.x;  // block 256
    const float* p = mask + (size_t)l * LDIM;
    float s = 0.f;
#pragma unroll
    for (int i = 0; i < 4; ++i) s += p[t + i * 256];
#pragma unroll
    for (int o = 16; o; o >>= 1) s += __shfl_xor_sync(0xffffffffu, s, o);
    __shared__ float ws[8];
    if ((t & 31) == 0) ws[t >> 5] = s;
    __syncthreads();
    if (t == 0) {
        float tot = 0.f;
#pragma unroll
        for (int j = 0; j < 8; ++j) tot += ws[j];
        g_nc[l] = tot;
    }
}

// ---------------- main fused kernel ----------------
// smem: sZ 2*128*132*4=135168 | sA 34816 | sW1 34816 | sB1 512 | sMask3 1536 | sStat 1024
#define SMEM_MAIN (135168 + 34816 + 34816 + 512 + 1536 + 1024)

__global__ __launch_bounds__(256, 1)
void main_kernel(const float* __restrict__ s_z, const float* __restrict__ mask,
                 const float* __restrict__ ln_g, const float* __restrict__ ln_b,
                 const float* __restrict__ b1p) {
    extern __shared__ __align__(16) char smem_raw[];
    float* sZ = (float*)smem_raw;                            // [2][128*132]
    __nv_bfloat16* sA  = (__nv_bfloat16*)(sZ + 2 * 128 * ZSTRIDE);
    __nv_bfloat16* sW1 = sA + CZ * ASTRIDE;
    float* sB1    = (float*)(sW1 + CZ * ASTRIDE);            // [128]
    float* sMask3 = sB1 + CZ;                                // [3][128]
    float2* sStat = (float2*)(sMask3 + 3 * CZ);              // [128] (mu, rstd)

    const int tid = threadIdx.x, lane = tid & 31, wid = tid >> 5;
    const int wm = wid & 3, wn = wid >> 2;
    const int cta = blockIdx.x;
    const int mblk = cta / NSUB, sub = cta % NSUB;
    const int l0 = (sub * LDIM) / NSUB, l1 = ((sub + 1) * LDIM) / NSUB;
    const int m0 = mblk * 128;

    for (int i = tid; i < CZ * ASTRIDE / 4; i += 256)
        ((uint2*)sW1)[i] = ((const uint2*)g_w1b)[i];
    if (tid < CZ) sB1[tid] = b1p[tid];
    const float4 gg = ((const float4*)ln_g)[lane];
    const float4 bb = ((const float4*)ln_b)[lane];

    // ldmatrix base addrs
    const unsigned sAb = (unsigned)__cvta_generic_to_shared(sA);
    const unsigned sWb = (unsigned)__cvta_generic_to_shared(sW1);
    const unsigned aRow = sAb + (unsigned)((wm * 32 + (lane & 15)) * (ASTRIDE * 2)) + ((lane >> 4) << 4);
    const unsigned bRow = sWb + (unsigned)((wn * 64 + (lane & 15)) * (ASTRIDE * 2)) + ((lane >> 4) << 4);

    float sr_acc[2][8][4];
#pragma unroll
    for (int mt = 0; mt < 2; ++mt)
#pragma unroll
        for (int nt = 0; nt < 8; ++nt)
#pragma unroll
            for (int j = 0; j < 4; ++j) sr_acc[mt][nt][j] = 0.f;
    float nr_acc = 0.f;

    // prologue prefetch of l0 (slot 0, buffer 0)
    {
        const float* src = s_z + (((size_t)l0 * LDIM + m0) << 7);
        for (int i = tid; i < 4096; i += 256) {
            int row = i >> 5, seg = i & 31;
            cp_async16(sZ + row * ZSTRIDE + seg * 4, src + row * 128 + seg * 4);
        }
        if (tid < 32) cp_async16(sMask3 + tid * 4, mask + (size_t)l0 * LDIM + m0 + tid * 4);
        asm volatile("cp.async.commit_group;\n");
    }

    for (int l = l0; l < l1; ++l) {
        const int it = l - l0;
        const int buf = it & 1;
        const int mi = it % 3;
        if (l + 1 < l1) {
            const int nb = buf ^ 1, ni = (it + 1) % 3;
            const float* src = s_z + (((size_t)(l + 1) * LDIM + m0) << 7);
            float* dst = sZ + nb * 128 * ZSTRIDE;
            for (int i = tid; i < 4096; i += 256) {
                int row = i >> 5, seg = i & 31;
                cp_async16(dst + row * ZSTRIDE + seg * 4, src + row * 128 + seg * 4);
            }
            if (tid < 32) cp_async16(sMask3 + ni * CZ + tid * 4,
                                     mask + (size_t)(l + 1) * LDIM + m0 + tid * 4);
            asm volatile("cp.async.commit_group;\n");
            asm volatile("cp.async.wait_group 1;\n");
        } else {
            asm volatile("cp.async.wait_group 0;\n");
        }
        __syncthreads();   // A: buffer ready

        const float* zb = sZ + buf * 128 * ZSTRIDE;

        // ---- phase 1: row stats, 2 threads per row, 2 shuffles ----
        {
            const int r = tid >> 1, h = tid & 1;
            const float4* base = (const float4*)(zb + r * ZSTRIDE + h * 64);
            float s = 0.f, q = 0.f;
#pragma unroll
            for (int i = 0; i < 16; ++i) {
                float4 x = base[i];
                s += x.x + x.y + x.z + x.w;
                q = fmaf(x.x, x.x, fmaf(x.y, x.y, fmaf(x.z, x.z, fmaf(x.w, x.w, q))));
            }
            s += __shfl_xor_sync(0xffffffffu, s, 1);
            q += __shfl_xor_sync(0xffffffffu, q, 1);
            if (h == 0) {
                const float mu = s * (1.f / 128.f);
                const float var = q * (1.f / 128.f) - mu * mu;
                sStat[r] = make_float2(mu, rsqrtf(var + 1e-5f));
            }
        }
        __syncthreads();   // C: stats ready

        // ---- phase 2: normalize + bf16 pack (lane = channel quad) ----
#pragma unroll 4
        for (int j = 0; j < 16; ++j) {
            const int row = wid * 16 + j;
            const float2 st = sStat[row];
            float4 x = ((const float4*)(zb + row * ZSTRIDE))[lane];
            const float y0 = (x.x - st.x) * st.y * gg.x + bb.x;
            const float y1 = (x.y - st.x) * st.y * gg.y + bb.y;
            const float y2 = (x.z - st.x) * st.y * gg.z + bb.z;
            const float y3 = (x.w - st.x) * st.y * gg.w + bb.w;
            __nv_bfloat162 p0 = __floats2bfloat162_rn(y0, y1);
            __nv_bfloat162 p1 = __floats2bfloat162_rn(y2, y3);
            uint2 pk = make_uint2(*(unsigned*)&p0, *(unsigned*)&p1);
            *reinterpret_cast<uint2*>(sA + row * ASTRIDE + lane * 4) = pk;
        }
        __syncthreads();   // B: sA ready

        // mask values for epilogue + nr accumulation (from slot mi)
        const float* mks = sMask3 + mi * CZ;
        float mkv[2][2];
        mkv[0][0] = mks[wm * 32 + (lane >> 2)];
        mkv[0][1] = mks[wm * 32 + 8 + (lane >> 2)];
        mkv[1][0] = mks[wm * 32 + 16 + (lane >> 2)];
        mkv[1][1] = mks[wm * 32 + 24 + (lane >> 2)];
        if (tid < CZ) nr_acc += mks[tid];

        // ---- GEMM1 via ldmatrix ----
        float d1[2][8][4];
#pragma unroll
        for (int mt = 0; mt < 2; ++mt)
#pragma unroll
            for (int nt = 0; nt < 8; ++nt)
#pragma unroll
                for (int j = 0; j < 4; ++j) d1[mt][nt][j] = 0.f;
#pragma unroll
        for (int kk = 0; kk < 8; ++kk) {
            const unsigned colb = kk * 32;
            unsigned a[2][4], b[8][2];
            ldsm_x4(aRow + colb, a[0][0], a[0][1], a[0][2], a[0][3]);
            ldsm_x4(aRow + 16 * (ASTRIDE * 2) + colb, a[1][0], a[1][1], a[1][2], a[1][3]);
#pragma unroll
            for (int ntp = 0; ntp < 4; ++ntp) {
                unsigned q0, q1, q2, q3;
                ldsm_x4(bRow + ntp * 16 * (ASTRIDE * 2) + colb, q0, q1, q2, q3);
                b[2 * ntp][0] = q0; b[2 * ntp][1] = q2;
                b[2 * ntp + 1][0] = q1; b[2 * ntp + 1][1] = q3;
            }
#pragma unroll
            for (int mt = 0; mt < 2; ++mt)
#pragma unroll
                for (int nt = 0; nt < 8; ++nt) mma16816(d1[mt][nt], a[mt], b[nt]);
        }

        // ---- epilogue: relu(.+b1)*mask, accumulate row sums (regs) + col sums (RED) ----
        float cs[8][2];
#pragma unroll
        for (int nt = 0; nt < 8; ++nt) { cs[nt][0] = 0.f; cs[nt][1] = 0.f; }
#pragma unroll
        for (int mt = 0; mt < 2; ++mt)
#pragma unroll
            for (int nt = 0; nt < 8; ++nt) {
                const int c = wn * 64 + nt * 8 + (lane & 3) * 2;
                const float bv0 = sB1[c], bv1 = sB1[c + 1];
                const float v0 = fmaxf(d1[mt][nt][0] + bv0, 0.f) * mkv[mt][0];
                const float v1 = fmaxf(d1[mt][nt][1] + bv1, 0.f) * mkv[mt][0];
                const float v2 = fmaxf(d1[mt][nt][2] + bv0, 0.f) * mkv[mt][1];
                const float v3 = fmaxf(d1[mt][nt][3] + bv1, 0.f) * mkv[mt][1];
                sr_acc[mt][nt][0] += v0; sr_acc[mt][nt][1] += v1;
                sr_acc[mt][nt][2] += v2; sr_acc[mt][nt][3] += v3;
                cs[nt][0] += v0 + v2;
                cs[nt][1] += v1 + v3;
            }
#pragma unroll
        for (int nt = 0; nt < 8; ++nt) {
#pragma unroll
            for (int o = 4; o <= 16; o <<= 1) {
                cs[nt][0] += __shfl_xor_sync(0xffffffffu, cs[nt][0], o);
                cs[nt][1] += __shfl_xor_sync(0xffffffffu, cs[nt][1], o);
            }
        }
        if (lane < 4) {
#pragma unroll
            for (int nt = 0; nt < 8; ++nt) {
                const int c = wn * 64 + nt * 8 + lane * 2;
                atomicAdd(&g_sc[l * CZ + c], cs[nt][0]);
                atomicAdd(&g_sc[l * CZ + c + 1], cs[nt][1]);
            }
        }
    }

    // ---- flush per-m masked h sums + nr ----
#pragma unroll
    for (int mt = 0; mt < 2; ++mt)
#pragma unroll
        for (int nt = 0; nt < 8; ++nt) {
            const int r = wm * 32 + mt * 16 + (lane >> 2);
            const int c = wn * 64 + nt * 8 + (lane & 3) * 2;
            atomicAdd(&g_sr[(size_t)(m0 + r) * CZ + c],     sr_acc[mt][nt][0]);
            atomicAdd(&g_sr[(size_t)(m0 + r) * CZ + c + 1], sr_acc[mt][nt][1]);
            atomicAdd(&g_sr[(size_t)(m0 + r + 8) * CZ + c],     sr_acc[mt][nt][2]);
            atomicAdd(&g_sr[(size_t)(m0 + r + 8) * CZ + c + 1], sr_acc[mt][nt][3]);
        }
    if (tid < CZ) atomicAdd(&g_nr[m0 + tid], nr_acc);
}

// ---------------- finalize: s_c/s_r via W2, write cat cols 0..255 ----------------
#define SMEM_CATF (128 * 132 * 4 + 512 + 1024)

__global__ __launch_bounds__(256)
void cat_finalize(const float* __restrict__ w2, const float* __restrict__ b2) {
    extern __shared__ __align__(16) char cf_raw[];
    float* sw2 = (float*)cf_raw;          // [128][132]
    float* sb2 = sw2 + 128 * 132;
    float* sh  = sb2 + 128;               // [256]
    const int tid = threadIdx.x;

    for (int i = tid; i < 128 * 32; i += 256) {
        int r = i >> 5, kq = i & 31;
        ((float4*)(sw2 + r * 132))[kq] = ((const float4*)(w2 + r * 128))[kq];
    }
    if (tid < 128) sb2[tid] = b2[tid];
    __syncthreads();

    for (int li = 0; li < 16; ++li) {
        const int l = blockIdx.x * 16 + li;
        if (tid < 128) sh[tid] = g_sc[l * CZ + tid];
        else           sh[tid] = g_sr[l * CZ + (tid - 128)];
        __syncthreads();
        const int c = tid & 127;
        const float nraw = (tid < 128) ? g_nc[l] : g_nr[l];
        const float* hv = sh + (tid & 128);
        float acc = sb2[c] * nraw;
#pragma unroll 8
        for (int k = 0; k < 32; ++k) {
            float4 w = ((const float4*)(sw2 + c * 132))[k];
            float4 h = ((const float4*)hv)[k];
            acc += w.x * h.x + w.y * h.y + w.z * h.z + w.w * h.w;
        }
        g_cat[(size_t)l * KCAT + tid] = to_tf32(acc / fmaxf(nraw, 1.f));
        __syncthreads();
    }
}

// ---------------- final projection: [1024 x 1280] @ [1024 x 1280]^T in tf32 ----------------
// tiles: M=128 (l), N=64 (d), k-chunks of 32; smem A[2][128][36], B[2][64][36]
#define SMEM_FG ((128 * 36 + 64 * 36) * 2 * 4)

__global__ __launch_bounds__(256, 2)
void final_gemm(const float* __restrict__ bc, float* __restrict__ out) {
    extern __shared__ __align__(16) float fg[];
    float* sAq = fg;                  // [2][128*36]
    float* sBq = fg + 2 * 128 * 36;   // [2][64*36]
    const int tid = threadIdx.x, lane = tid & 31, wid = tid >> 5;
    const int wm = wid >> 1, wn = wid & 1;
    const int lbase = blockIdx.y * 128, dbase = blockIdx.x * 64;
    const int NCH = KCAT / 32;   // 40

    float acc[2][4][4];
#pragma unroll
    for (int mt = 0; mt < 2; ++mt)
#pragma unroll
        for (int nt = 0; nt < 4; ++nt)
#pragma unroll
            for (int j = 0; j < 4; ++j) acc[mt][nt][j] = 0.f;

    {
        for (int i = tid; i < 1024; i += 256) {
            int row = i >> 3, seg = i & 7;
            cp_async16(sAq + row * 36 + seg * 4, g_cat + (size_t)(lbase + row) * KCAT + seg * 4);
        }
        for (int i = tid; i < 512; i += 256) {
            int row = i >> 3, seg = i & 7;
            cp_async16(sBq + row * 36 + seg * 4, g_wct + (size_t)(dbase + row) * KCAT + seg * 4);
        }
        asm volatile("cp.async.commit_group;\n");
    }

    for (int ch = 0; ch < NCH; ++ch) {
        const int buf = ch & 1;
        if (ch + 1 < NCH) {
            const int nb = buf ^ 1;
            const size_t kb = (size_t)(ch + 1) * 32;
            for (int i = tid; i < 1024; i += 256) {
                int row = i >> 3, seg = i & 7;
                cp_async16(sAq + nb * 128 * 36 + row * 36 + seg * 4,
                           g_cat + (size_t)(lbase + row) * KCAT + kb + seg * 4);
            }
            for (int i = tid; i < 512; i += 256) {
                int row = i >> 3, seg = i & 7;
                cp_async16(sBq + nb * 64 * 36 + row * 36 + seg * 4,
                           g_wct + (size_t)(dbase + row) * KCAT + kb + seg * 4);
            }
            asm volatile("cp.async.commit_group;\n");
            asm volatile("cp.async.wait_group 1;\n");
        } else {
            asm volatile("cp.async.wait_group 0;\n");
        }
        __syncthreads();

        const float* Ab = sAq + buf * 128 * 36;
        const float* Bb = sBq + buf * 64 * 36;
#pragma unroll
        for (int ks = 0; ks < 4; ++ks) {
            const int k0 = ks * 8 + (lane & 3);
            unsigned a[2][4], b[4][2];
#pragma unroll
            for (int mt = 0; mt < 2; ++mt) {
                const int r = wm * 32 + mt * 16 + (lane >> 2);
                a[mt][0] = __float_as_uint(Ab[r * 36 + k0]);
                a[mt][1] = __float_as_uint(Ab[(r + 8) * 36 + k0]);
                a[mt][2] = __float_as_uint(Ab[r * 36 + k0 + 4]);
                a[mt][3] = __float_as_uint(Ab[(r + 8) * 36 + k0 + 4]);
            }
#pragma unroll
            for (int nt = 0; nt < 4; ++nt) {
                const int n = wn * 32 + nt * 8 + (lane >> 2);
                b[nt][0] = __float_as_uint(Bb[n * 36 + k0]);
                b[nt][1] = __float_as_uint(Bb[n * 36 + k0 + 4]);
            }
#pragma unroll
            for (int mt = 0; mt < 2; ++mt)
#pragma unroll
                for (int nt = 0; nt < 4; ++nt) mma1688_tf32(acc[mt][nt], a[mt], b[nt]);
        }
        __syncthreads();
    }

#pragma unroll
    for (int mt = 0; mt < 2; ++mt)
#pragma unroll
        for (int nt = 0; nt < 4; ++nt) {
            const int r = wm * 32 + mt * 16 + (lane >> 2);
            const int c = wn * 32 + nt * 8 + (lane & 3) * 2;
            const int gr = lbase + r, gc = dbase + c;
            const float b0 = __ldg(&bc[gc]), b1v = __ldg(&bc[gc + 1]);
            out[(size_t)gr * CS + gc]           = acc[mt][nt][0] + b0;
            out[(size_t)gr * CS + gc + 1]       = acc[mt][nt][1] + b1v;
            out[(size_t)(gr + 8) * CS + gc]     = acc[mt][nt][2] + b0;
            out[(size_t)(gr + 8) * CS + gc + 1] = acc[mt][nt][3] + b1v;
        }
}

// ---------------- launcher ----------------
extern "C" void kernel_launch(void* const* d_in, const int* in_sizes, int n_in,
                              void* d_out, int out_size) {
    const float* s_z    = (const float*)d_in[0];
    const float* s_s_in = (const float*)d_in[1];
    const float* mask   = (const float*)d_in[2];
    const float* ln_g   = (const float*)d_in[3];
    const float* ln_b   = (const float*)d_in[4];
    const float* w1     = (const float*)d_in[5];
    const float* b1     = (const float*)d_in[6];
    const float* w2     = (const float*)d_in[7];
    const float* b2     = (const float*)d_in[8];
    const float* wc     = (const float*)d_in[9];
    const float* bc     = (const float*)d_in[10];
    float* out = (float*)d_out;
    (void)in_sizes; (void)n_in; (void)out_size;

    cudaFuncSetAttribute(main_kernel, cudaFuncAttributeMaxDynamicSharedMemorySize, SMEM_MAIN);
    cudaFuncSetAttribute(cat_finalize, cudaFuncAttributeMaxDynamicSharedMemorySize, SMEM_CATF);
    cudaFuncSetAttribute(final_gemm, cudaFuncAttributeMaxDynamicSharedMemorySize, SMEM_FG);

    prep_w1<<<(CZ * ASTRIDE + 255) / 256, 256>>>(w1);
    prep_wct<<<(CS * KCAT + 255) / 256, 256>>>(wc);
    prep_catss<<<(LDIM * CS + 255) / 256, 256>>>(s_s_in);
    zero_acc<<<(LDIM * CZ + 255) / 256, 256>>>();
    norm_c<<<LDIM, 256>>>(mask);
    main_kernel<<<GRID_MAIN, 256, SMEM_MAIN>>>(s_z, mask, ln_g, ln_b, b1);
    cat_finalize<<<64, 256, SMEM_CATF>>>(w2, b2);
    final_gemm<<<dim3(16, 8), 256, SMEM_FG>>>(bc, out);
}

// round 10
// speedup vs baseline: 1.4944x; 1.0018x over previous
#include <cuda_runtime.h>
#include <cuda_bf16.h>

// ---------------- problem constants ----------------
#define LDIM 1024
#define CZ   128
#define CS   1024
#define KCAT 1280
#define ASTRIDE 136          // padded bf16 row stride
#define ZSTRIDE 132          // padded fp32 row stride for sZ
#define NSUB  19
#define NMBLK 8
#define GRID_MAIN (NSUB * NMBLK)   // 152

// ---------------- device scratch ----------------
__device__ __align__(16) float g_sc[LDIM * CZ];
__device__ __align__(16) float g_sr[LDIM * CZ];
__device__ float g_nc[LDIM];
__device__ float g_nr[LDIM];
__device__ float g_b1p[CZ];                                 // b1 + W1 @ ln_b
__device__ __align__(16) __nv_bfloat16 g_w1b[CZ * ASTRIDE]; // W1 * ln_g (bf16, padded)
__device__ __align__(16) float g_wct[(size_t)CS * KCAT];    // tf32-rounded wc
__device__ __align__(16) float g_cat[(size_t)LDIM * KCAT];  // tf32 [s_c|s_r|s_s_in]

// ---------------- helpers ----------------
__device__ __forceinline__ float to_tf32(float v) {
    float r; asm("cvt.rna.tf32.f32 %0, %1;" : "=f"(r) : "f"(v)); return r;
}
__device__ __forceinline__ void mma16816(float* d, const unsigned* a, const unsigned* b) {
    asm volatile(
        "mma.sync.aligned.m16n8k16.row.col.f32.bf16.bf16.f32 "
        "{%0,%1,%2,%3}, {%4,%5,%6,%7}, {%8,%9}, {%0,%1,%2,%3};\n"
        : "+f"(d[0]), "+f"(d[1]), "+f"(d[2]), "+f"(d[3])
        : "r"(a[0]), "r"(a[1]), "r"(a[2]), "r"(a[3]), "r"(b[0]), "r"(b[1]));
}
__device__ __forceinline__ void mma1688_tf32(float* d, const unsigned* a, const unsigned* b) {
    asm volatile(
        "mma.sync.aligned.m16n8k8.row.col.f32.tf32.tf32.f32 "
        "{%0,%1,%2,%3}, {%4,%5,%6,%7}, {%8,%9}, {%0,%1,%2,%3};\n"
        : "+f"(d[0]), "+f"(d[1]), "+f"(d[2]), "+f"(d[3])
        : "r"(a[0]), "r"(a[1]), "r"(a[2]), "r"(a[3]), "r"(b[0]), "r"(b[1]));
}
__device__ __forceinline__ void ldsm_x4(unsigned addr, unsigned& r0, unsigned& r1,
                                        unsigned& r2, unsigned& r3) {
    asm volatile("ldmatrix.sync.aligned.m8n8.x4.shared.b16 {%0,%1,%2,%3}, [%4];"
                 : "=r"(r0), "=r"(r1), "=r"(r2), "=r"(r3) : "r"(addr));
}
__device__ __forceinline__ void cp_async16(void* sptr, const void* gptr) {
    unsigned s = (unsigned)__cvta_generic_to_shared(sptr);
    asm volatile("cp.async.cg.shared.global [%0], [%1], 16;\n" :: "r"(s), "l"(gptr));
}

// ---------------- prep kernels ----------------
// threads 0-127: W1' = W1 * ln_g (bf16, padded); threads 128-255: b1' = b1 + W1 @ ln_b
__global__ void prep_w1b1(const float* __restrict__ w1, const float* __restrict__ b1,
                          const float* __restrict__ ln_g, const float* __restrict__ ln_b) {
    __shared__ float sb[CZ];
    const int t = threadIdx.x;
    if (t < CZ) sb[t] = ln_b[t];
    __syncthreads();
    if (t < CZ) {
        const float g = ln_g[t];   // column t
        for (int d = 0; d < CZ; ++d)
            g_w1b[d * ASTRIDE + t] = __float2bfloat16(w1[d * CZ + t] * g);
        for (int k = CZ; k < ASTRIDE; ++k) g_w1b[t * ASTRIDE + k] = __float2bfloat16(0.f);
    } else {
        const int d = t - CZ;
        float acc = b1[d];
#pragma unroll 8
        for (int k = 0; k < CZ; ++k) acc += w1[d * CZ + k] * sb[k];
        g_b1p[d] = acc;
    }
}
__global__ void prep_wct(const float* __restrict__ wc) {
    int i = blockIdx.x * 256 + threadIdx.x;
    if (i < CS * KCAT) g_wct[i] = to_tf32(wc[i]);
}
__global__ void prep_catss(const float* __restrict__ s_s_in) {
    int i = blockIdx.x * 256 + threadIdx.x;
    if (i >= LDIM * CS) return;
    int l = i >> 10, k = i & 1023;
    g_cat[(size_t)l * KCAT + 256 + k] = to_tf32(s_s_in[i]);
}
// mask row sums -> g_nc; also zero g_sc/g_sr/g_nr
__global__ void norm_c(const float* __restrict__ mask) {
    const int l = blockIdx.x, t = threadIdx.x;  // block 256
    if (t < 128) g_sc[l * CZ + t] = 0.f;
    else         g_sr[l * CZ + (t - 128)] = 0.f;
    if (t == 0) g_nr[l] = 0.f;
    const float* p = mask + (size_t)l * LDIM;
    float s = 0.f;
#pragma unroll
    for (int i = 0; i < 4; ++i) s += p[t + i * 256];
#pragma unroll
    for (int o = 16; o; o >>= 1) s += __shfl_xor_sync(0xffffffffu, s, o);
    __shared__ float ws[8];
    if ((t & 31) == 0) ws[t >> 5] = s;
    __syncthreads();
    if (t == 0) {
        float tot = 0.f;
#pragma unroll
        for (int j = 0; j < 8; ++j) tot += ws[j];
        g_nc[l] = tot;
    }
}

// ---------------- main fused kernel ----------------
// smem: sZ 2*128*132*4=135168 | sA 34816 | sW1 34816 | sB1 512 | sMask3 1536 | sStat 1024
#define SMEM_MAIN (135168 + 34816 + 34816 + 512 + 1536 + 1024)

__global__ __launch_bounds__(256, 1)
void main_kernel(const float* __restrict__ s_z, const float* __restrict__ mask) {
    extern __shared__ __align__(16) char smem_raw[];
    float* sZ = (float*)smem_raw;                            // [2][128*132]
    __nv_bfloat16* sA  = (__nv_bfloat16*)(sZ + 2 * 128 * ZSTRIDE);
    __nv_bfloat16* sW1 = sA + CZ * ASTRIDE;
    float* sB1    = (float*)(sW1 + CZ * ASTRIDE);            // [128]
    float* sMask3 = sB1 + CZ;                                // [3][128]
    float2* sStat = (float2*)(sMask3 + 3 * CZ);              // [128] (rstd, -mu*rstd)

    const int tid = threadIdx.x, lane = tid & 31, wid = tid >> 5;
    const int wm = wid & 3, wn = wid >> 2;
    const int cta = blockIdx.x;
    const int mblk = cta / NSUB, sub = cta % NSUB;
    const int l0 = (sub * LDIM) / NSUB, l1 = ((sub + 1) * LDIM) / NSUB;
    const int m0 = mblk * 128;

    for (int i = tid; i < CZ * ASTRIDE / 4; i += 256)
        ((uint2*)sW1)[i] = ((const uint2*)g_w1b)[i];
    if (tid < CZ) sB1[tid] = g_b1p[tid];

    // ldmatrix base addrs
    const unsigned sAb = (unsigned)__cvta_generic_to_shared(sA);
    const unsigned sWb = (unsigned)__cvta_generic_to_shared(sW1);
    const unsigned aRow = sAb + (unsigned)((wm * 32 + (lane & 15)) * (ASTRIDE * 2)) + ((lane >> 4) << 4);
    const unsigned bRow = sWb + (unsigned)((wn * 64 + (lane & 15)) * (ASTRIDE * 2)) + ((lane >> 4) << 4);

    float sr_acc[2][8][4];
#pragma unroll
    for (int mt = 0; mt < 2; ++mt)
#pragma unroll
        for (int nt = 0; nt < 8; ++nt)
#pragma unroll
            for (int j = 0; j < 4; ++j) sr_acc[mt][nt][j] = 0.f;
    float nr_acc = 0.f;

    // prologue prefetch of l0 (slot 0, buffer 0)
    {
        const float* src = s_z + (((size_t)l0 * LDIM + m0) << 7);
        for (int i = tid; i < 4096; i += 256) {
            int row = i >> 5, seg = i & 31;
            cp_async16(sZ + row * ZSTRIDE + seg * 4, src + row * 128 + seg * 4);
        }
        if (tid < 32) cp_async16(sMask3 + tid * 4, mask + (size_t)l0 * LDIM + m0 + tid * 4);
        asm volatile("cp.async.commit_group;\n");
    }

    for (int l = l0; l < l1; ++l) {
        const int it = l - l0;
        const int buf = it & 1;
        const int mi = it % 3;
        if (l + 1 < l1) {
            const int nb = buf ^ 1, ni = (it + 1) % 3;
            const float* src = s_z + (((size_t)(l + 1) * LDIM + m0) << 7);
            float* dst = sZ + nb * 128 * ZSTRIDE;
            for (int i = tid; i < 4096; i += 256) {
                int row = i >> 5, seg = i & 31;
                cp_async16(dst + row * ZSTRIDE + seg * 4, src + row * 128 + seg * 4);
            }
            if (tid < 32) cp_async16(sMask3 + ni * CZ + tid * 4,
                                     mask + (size_t)(l + 1) * LDIM + m0 + tid * 4);
            asm volatile("cp.async.commit_group;\n");
            asm volatile("cp.async.wait_group 1;\n");
        } else {
            asm volatile("cp.async.wait_group 0;\n");
        }
        __syncthreads();   // A: buffer ready

        const float* zb = sZ + buf * 128 * ZSTRIDE;

        // ---- phase 1: row stats, 2 threads per row, 2 shuffles ----
        {
            const int r = tid >> 1, h = tid & 1;
            const float4* base = (const float4*)(zb + r * ZSTRIDE + h * 64);
            float s = 0.f, q = 0.f;
#pragma unroll
            for (int i = 0; i < 16; ++i) {
                float4 x = base[i];
                s += x.x + x.y + x.z + x.w;
                q = fmaf(x.x, x.x, fmaf(x.y, x.y, fmaf(x.z, x.z, fmaf(x.w, x.w, q))));
            }
            s += __shfl_xor_sync(0xffffffffu, s, 1);
            q += __shfl_xor_sync(0xffffffffu, q, 1);
            if (h == 0) {
                const float mu = s * (1.f / 128.f);
                const float var = q * (1.f / 128.f) - mu * mu;
                const float rstd = rsqrtf(var + 1e-5f);
                sStat[r] = make_float2(rstd, -mu * rstd);
            }
        }
        __syncthreads();   // C: stats ready

        // ---- phase 2: normalize + bf16 pack (ln folded into W1'/b1') ----
#pragma unroll 4
        for (int j = 0; j < 16; ++j) {
            const int row = wid * 16 + j;
            const float2 st = sStat[row];
            float4 x = ((const float4*)(zb + row * ZSTRIDE))[lane];
            const float y0 = fmaf(x.x, st.x, st.y);
            const float y1 = fmaf(x.y, st.x, st.y);
            const float y2 = fmaf(x.z, st.x, st.y);
            const float y3 = fmaf(x.w, st.x, st.y);
            __nv_bfloat162 p0 = __floats2bfloat162_rn(y0, y1);
            __nv_bfloat162 p1 = __floats2bfloat162_rn(y2, y3);
            uint2 pk = make_uint2(*(unsigned*)&p0, *(unsigned*)&p1);
            *reinterpret_cast<uint2*>(sA + row * ASTRIDE + lane * 4) = pk;
        }
        __syncthreads();   // B: sA ready

        // mask values for epilogue + nr accumulation (from slot mi)
        const float* mks = sMask3 + mi * CZ;
        float mkv[2][2];
        mkv[0][0] = mks[wm * 32 + (lane >> 2)];
        mkv[0][1] = mks[wm * 32 + 8 + (lane >> 2)];
        mkv[1][0] = mks[wm * 32 + 16 + (lane >> 2)];
        mkv[1][1] = mks[wm * 32 + 24 + (lane >> 2)];
        if (tid < CZ) nr_acc += mks[tid];

        // ---- GEMM1 via ldmatrix ----
        float d1[2][8][4];
#pragma unroll
        for (int mt = 0; mt < 2; ++mt)
#pragma unroll
            for (int nt = 0; nt < 8; ++nt)
#pragma unroll
                for (int j = 0; j < 4; ++j) d1[mt][nt][j] = 0.f;
#pragma unroll
        for (int kk = 0; kk < 8; ++kk) {
            const unsigned colb = kk * 32;
            unsigned a[2][4], b[8][2];
            ldsm_x4(aRow + colb, a[0][0], a[0][1], a[0][2], a[0][3]);
            ldsm_x4(aRow + 16 * (ASTRIDE * 2) + colb, a[1][0], a[1][1], a[1][2], a[1][3]);
#pragma unroll
            for (int ntp = 0; ntp < 4; ++ntp) {
                unsigned q0, q1, q2, q3;
                ldsm_x4(bRow + ntp * 16 * (ASTRIDE * 2) + colb, q0, q1, q2, q3);
                b[2 * ntp][0] = q0; b[2 * ntp][1] = q2;
                b[2 * ntp + 1][0] = q1; b[2 * ntp + 1][1] = q3;
            }
#pragma unroll
            for (int mt = 0; mt < 2; ++mt)
#pragma unroll
                for (int nt = 0; nt < 8; ++nt) mma16816(d1[mt][nt], a[mt], b[nt]);
        }

        // ---- epilogue: relu(.+b1')*mask, accumulate row sums (regs) + col sums ----
        float cs[8][2];
#pragma unroll
        for (int nt = 0; nt < 8; ++nt) { cs[nt][0] = 0.f; cs[nt][1] = 0.f; }
#pragma unroll
        for (int mt = 0; mt < 2; ++mt)
#pragma unroll
            for (int nt = 0; nt < 8; ++nt) {
                const int c = wn * 64 + nt * 8 + (lane & 3) * 2;
                const float bv0 = sB1[c], bv1 = sB1[c + 1];
                const float v0 = fmaxf(d1[mt][nt][0] + bv0, 0.f) * mkv[mt][0];
                const float v1 = fmaxf(d1[mt][nt][1] + bv1, 0.f) * mkv[mt][0];
                const float v2 = fmaxf(d1[mt][nt][2] + bv0, 0.f) * mkv[mt][1];
                const float v3 = fmaxf(d1[mt][nt][3] + bv1, 0.f) * mkv[mt][1];
                sr_acc[mt][nt][0] += v0; sr_acc[mt][nt][1] += v1;
                sr_acc[mt][nt][2] += v2; sr_acc[mt][nt][3] += v3;
                cs[nt][0] += v0 + v2;
                cs[nt][1] += v1 + v3;
            }
#pragma unroll
        for (int nt = 0; nt < 8; ++nt) {
#pragma unroll
            for (int o = 4; o <= 16; o <<= 1) {
                cs[nt][0] += __shfl_xor_sync(0xffffffffu, cs[nt][0], o);
                cs[nt][1] += __shfl_xor_sync(0xffffffffu, cs[nt][1], o);
            }
        }
        if (lane < 4) {
#pragma unroll
            for (int nt = 0; nt < 8; ++nt) {
                const int c = wn * 64 + nt * 8 + lane * 2;
                atomicAdd(&g_sc[l * CZ + c], cs[nt][0]);
                atomicAdd(&g_sc[l * CZ + c + 1], cs[nt][1]);
            }
        }
    }

    // ---- flush per-m masked h sums + nr ----
#pragma unroll
    for (int mt = 0; mt < 2; ++mt)
#pragma unroll
        for (int nt = 0; nt < 8; ++nt) {
            const int r = wm * 32 + mt * 16 + (lane >> 2);
            const int c = wn * 64 + nt * 8 + (lane & 3) * 2;
            atomicAdd(&g_sr[(size_t)(m0 + r) * CZ + c],     sr_acc[mt][nt][0]);
            atomicAdd(&g_sr[(size_t)(m0 + r) * CZ + c + 1], sr_acc[mt][nt][1]);
            atomicAdd(&g_sr[(size_t)(m0 + r + 8) * CZ + c],     sr_acc[mt][nt][2]);
            atomicAdd(&g_sr[(size_t)(m0 + r + 8) * CZ + c + 1], sr_acc[mt][nt][3]);
        }
    if (tid < CZ) atomicAdd(&g_nr[m0 + tid], nr_acc);
}

// ---------------- finalize: s_c/s_r via W2, write cat cols 0..255 ----------------
#define SMEM_CATF (128 * 132 * 4 + 512 + 1024)

__global__ __launch_bounds__(256)
void cat_finalize(const float* __restrict__ w2, const float* __restrict__ b2) {
    extern __shared__ __align__(16) char cf_raw[];
    float* sw2 = (float*)cf_raw;          // [128][132]
    float* sb2 = sw2 + 128 * 132;
    float* sh  = sb2 + 128;               // [256]
    const int tid = threadIdx.x;

    for (int i = tid; i < 128 * 32; i += 256) {
        int r = i >> 5, kq = i & 31;
        ((float4*)(sw2 + r * 132))[kq] = ((const float4*)(w2 + r * 128))[kq];
    }
    if (tid < 128) sb2[tid] = b2[tid];
    __syncthreads();

    for (int li = 0; li < 16; ++li) {
        const int l = blockIdx.x * 16 + li;
        if (tid < 128) sh[tid] = g_sc[l * CZ + tid];
        else           sh[tid] = g_sr[l * CZ + (tid - 128)];
        __syncthreads();
        const int c = tid & 127;
        const float nraw = (tid < 128) ? g_nc[l] : g_nr[l];
        const float* hv = sh + (tid & 128);
        float acc = sb2[c] * nraw;
#pragma unroll 8
        for (int k = 0; k < 32; ++k) {
            float4 w = ((const float4*)(sw2 + c * 132))[k];
            float4 h = ((const float4*)hv)[k];
            acc += w.x * h.x + w.y * h.y + w.z * h.z + w.w * h.w;
        }
        g_cat[(size_t)l * KCAT + tid] = to_tf32(acc / fmaxf(nraw, 1.f));
        __syncthreads();
    }
}

// ---------------- final projection: [1024 x 1280] @ [1024 x 1280]^T in tf32 ----------------
#define SMEM_FG ((128 * 36 + 64 * 36) * 2 * 4)

__global__ __launch_bounds__(256, 2)
void final_gemm(const float* __restrict__ bc, float* __restrict__ out) {
    extern __shared__ __align__(16) float fg[];
    float* sAq = fg;                  // [2][128*36]
    float* sBq = fg + 2 * 128 * 36;   // [2][64*36]
    const int tid = threadIdx.x, lane = tid & 31, wid = tid >> 5;
    const int wm = wid >> 1, wn = wid & 1;
    const int lbase = blockIdx.y * 128, dbase = blockIdx.x * 64;
    const int NCH = KCAT / 32;   // 40

    float acc[2][4][4];
#pragma unroll
    for (int mt = 0; mt < 2; ++mt)
#pragma unroll
        for (int nt = 0; nt < 4; ++nt)
#pragma unroll
            for (int j = 0; j < 4; ++j) acc[mt][nt][j] = 0.f;

    {
        for (int i = tid; i < 1024; i += 256) {
            int row = i >> 3, seg = i & 7;
            cp_async16(sAq + row * 36 + seg * 4, g_cat + (size_t)(lbase + row) * KCAT + seg * 4);
        }
        for (int i = tid; i < 512; i += 256) {
            int row = i >> 3, seg = i & 7;
            cp_async16(sBq + row * 36 + seg * 4, g_wct + (size_t)(dbase + row) * KCAT + seg * 4);
        }
        asm volatile("cp.async.commit_group;\n");
    }

    for (int ch = 0; ch < NCH; ++ch) {
        const int buf = ch & 1;
        if (ch + 1 < NCH) {
            const int nb = buf ^ 1;
            const size_t kb = (size_t)(ch + 1) * 32;
            for (int i = tid; i < 1024; i += 256) {
                int row = i >> 3, seg = i & 7;
                cp_async16(sAq + nb * 128 * 36 + row * 36 + seg * 4,
                           g_cat + (size_t)(lbase + row) * KCAT + kb + seg * 4);
            }
            for (int i = tid; i < 512; i += 256) {
                int row = i >> 3, seg = i & 7;
                cp_async16(sBq + nb * 64 * 36 + row * 36 + seg * 4,
                           g_wct + (size_t)(dbase + row) * KCAT + kb + seg * 4);
            }
            asm volatile("cp.async.commit_group;\n");
            asm volatile("cp.async.wait_group 1;\n");
        } else {
            asm volatile("cp.async.wait_group 0;\n");
        }
        __syncthreads();

        const float* Ab = sAq + buf * 128 * 36;
        const float* Bb = sBq + buf * 64 * 36;
#pragma unroll
        for (int ks = 0; ks < 4; ++ks) {
            const int k0 = ks * 8 + (lane & 3);
            unsigned a[2][4], b[4][2];
#pragma unroll
            for (int mt = 0; mt < 2; ++mt) {
                const int r = wm * 32 + mt * 16 + (lane >> 2);
                a[mt][0] = __float_as_uint(Ab[r * 36 + k0]);
                a[mt][1] = __float_as_uint(Ab[(r + 8) * 36 + k0]);
                a[mt][2] = __float_as_uint(Ab[r * 36 + k0 + 4]);
                a[mt][3] = __float_as_uint(Ab[(r + 8) * 36 + k0 + 4]);
            }
#pragma unroll
            for (int nt = 0; nt < 4; ++nt) {
                const int n = wn * 32 + nt * 8 + (lane >> 2);
                b[nt][0] = __float_as_uint(Bb[n * 36 + k0]);
                b[nt][1] = __float_as_uint(Bb[n * 36 + k0 + 4]);
            }
#pragma unroll
            for (int mt = 0; mt < 2; ++mt)
#pragma unroll
                for (int nt = 0; nt < 4; ++nt) mma1688_tf32(acc[mt][nt], a[mt], b[nt]);
        }
        __syncthreads();
    }

#pragma unroll
    for (int mt = 0; mt < 2; ++mt)
#pragma unroll
        for (int nt = 0; nt < 4; ++nt) {
            const int r = wm * 32 + mt * 16 + (lane >> 2);
            const int c = wn * 32 + nt * 8 + (lane & 3) * 2;
            const int gr = lbase + r, gc = dbase + c;
            const float b0 = __ldg(&bc[gc]), b1v = __ldg(&bc[gc + 1]);
            out[(size_t)gr * CS + gc]           = acc[mt][nt][0] + b0;
            out[(size_t)gr * CS + gc + 1]       = acc[mt][nt][1] + b1v;
            out[(size_t)(gr + 8) * CS + gc]     = acc[mt][nt][2] + b0;
            out[(size_t)(gr + 8) * CS + gc + 1] = acc[mt][nt][3] + b1v;
        }
}

// ---------------- launcher ----------------
extern "C" void kernel_launch(void* const* d_in, const int* in_sizes, int n_in,
                              void* d_out, int out_size) {
    const float* s_z    = (const float*)d_in[0];
    const float* s_s_in = (const float*)d_in[1];
    const float* mask   = (const float*)d_in[2];
    const float* ln_g   = (const float*)d_in[3];
    const float* ln_b   = (const float*)d_in[4];
    const float* w1     = (const float*)d_in[5];
    const float* b1     = (const float*)d_in[6];
    const float* w2     = (const float*)d_in[7];
    const float* b2     = (const float*)d_in[8];
    const float* wc     = (const float*)d_in[9];
    const float* bc     = (const float*)d_in[10];
    float* out = (float*)d_out;
    (void)in_sizes; (void)n_in; (void)out_size;

    cudaFuncSetAttribute(main_kernel, cudaFuncAttributeMaxDynamicSharedMemorySize, SMEM_MAIN);
    cudaFuncSetAttribute(cat_finalize, cudaFuncAttributeMaxDynamicSharedMemorySize, SMEM_CATF);
    cudaFuncSetAttribute(final_gemm, cudaFuncAttributeMaxDynamicSharedMemorySize, SMEM_FG);

    prep_w1b1<<<1, 256>>>(w1, b1, ln_g, ln_b);
    prep_wct<<<(CS * KCAT + 255) / 256, 256>>>(wc);
    prep_catss<<<(LDIM * CS + 255) / 256, 256>>>(s_s_in);
    norm_c<<<LDIM, 256>>>(mask);
    main_kernel<<<GRID_MAIN, 256, SMEM_MAIN>>>(s_z, mask);
    cat_finalize<<<64, 256, SMEM_CATF>>>(w2, b2);
    final_gemm<<<dim3(16, 8), 256, SMEM_FG>>>(bc, out);
}